// round 13
// baseline (speedup 1.0000x reference)
#include <cuda_runtime.h>
#include <math.h>

#define T_TOK   2048
#define H_DIM   128
#define H4_DIM  512
#define N_NODES 256
#define TB      8    // tokens per chunk
#define NC      4    // token chunks in grid (covers 32 tokens; stride loop beyond)

// Scratch (allocation-free per harness rules)
__device__ int   g_count[N_NODES];
__device__ int   g_tokens[N_NODES * T_TOK];
__device__ float g_h[T_TOK * H4_DIM];   // 4 MB intermediate (L2-resident)

// Single-launch prep: 1024 threads, smem counters, 2 tokens/thread.
__global__ void prep_kernel(const int* __restrict__ node_ind) {
    __shared__ int scnt[N_NODES];
    const int tid = threadIdx.x;
    if (tid < N_NODES) scnt[tid] = 0;
    __syncthreads();
    #pragma unroll
    for (int t = tid; t < T_TOK; t += 1024) {
        int n = node_ind[t];
        int pos = atomicAdd(&scnt[n], 1);
        g_tokens[n * T_TOK + pos] = t;
    }
    __syncthreads();
    if (tid < N_NODES) g_count[tid] = scnt[tid];
}

__device__ __forceinline__ float gelu_exact(float v) {
    return 0.5f * v * (1.0f + erff(v * 0.70710678118654752f));
}

// ============================================================================
// Layer 1: grid = N_NODES*16*NC. bid -> (n, q rows-of-32, tc token-chunk).
// 128 thr / 4 warps (high occupancy for DRAM MLP). Warp w owns rows
// w*8 + it*4 + g (it=0..1, g=0..3). lane=(g<<3)|c; activation float4 [j*8+c]:
// 1 wavefront (broadcast over g), xv shared by both it rows.
// Distributing butterfly: lane c ends with token c's sum -> gelu once/lane.
// ============================================================================
__global__ __launch_bounds__(128, 6)
void layer1_kernel(const float* __restrict__ x,
                   const float* __restrict__ W1,
                   const float* __restrict__ b1) {
    __shared__ float xs[TB][H_DIM];   // 4 KB
    __shared__ int   stoks[TB];

    const int b  = blockIdx.x;
    const int tc = b & (NC - 1);
    const int q  = (b >> 2) & 15;
    const int n  = b >> 6;
    const int base0 = tc * TB;

    const int tid = threadIdx.x;

    // Speculative token-id load (independent of count; address always valid)
    int spec_tok = 0;
    if (tid < TB) spec_tok = g_tokens[n * T_TOK + base0 + tid];
    const int nt_total = g_count[n];
    if (base0 >= nt_total) return;

    const int w    = tid >> 5;
    const int lane = tid & 31;
    const int g    = lane >> 3;   // row slot 0..3 (broadcast group)
    const int c    = lane & 7;    // k-chunk 0..7

    const float* W1c = W1 + (size_t)n * H4_DIM * H_DIM + (size_t)q * 32 * H_DIM;
    const float* b1c = b1 + n * H4_DIM + q * 32;

    float4 wv[2][4];
    float  bias[2];
    #pragma unroll
    for (int it = 0; it < 2; it++) {
        const int rr = w * 8 + it * 4 + g;
        const float4* wr = (const float4*)(W1c + (size_t)rr * H_DIM);
        #pragma unroll
        for (int j = 0; j < 4; j++) wv[it][j] = wr[j * 8 + c];
        bias[it] = b1c[rr];
    }

    for (int base = base0; base < nt_total; base += NC * TB) {
        const int nt = min(TB, nt_total - base);

        __syncthreads();
        if (tid < nt)
            stoks[tid] = (base == base0) ? spec_tok
                                         : g_tokens[n * T_TOK + base + tid];
        __syncthreads();
        #pragma unroll
        for (int k = 0; k < 2; k++) {
            int idx = tid + k * 128;
            int tk = idx >> 5;
            int l4 = idx & 31;
            if (tk < nt)
                ((float4*)xs[tk])[l4] =
                    ((const float4*)(x + (size_t)stoks[tk] * H_DIM))[l4];
        }
        __syncthreads();

        float acc[2][TB];
        #pragma unroll
        for (int it = 0; it < 2; it++)
            #pragma unroll
            for (int t = 0; t < TB; t++) acc[it][t] = 0.f;

        #pragma unroll
        for (int t = 0; t < TB; t++) {
            if (t < nt) {
                #pragma unroll
                for (int j = 0; j < 4; j++) {
                    float4 xv = ((const float4*)xs[t])[j * 8 + c];
                    acc[0][t] += wv[0][j].x * xv.x + wv[0][j].y * xv.y
                               + wv[0][j].z * xv.z + wv[0][j].w * xv.w;
                    acc[1][t] += wv[1][j].x * xv.x + wv[1][j].y * xv.y
                               + wv[1][j].z * xv.z + wv[1][j].w * xv.w;
                }
            }
        }

        // Distributing butterfly over the 8-lane group: lane c ends with
        // token c's full sum.
        #pragma unroll
        for (int it = 0; it < 2; it++) {
            float a0 = acc[it][0], a1 = acc[it][1], a2 = acc[it][2], a3 = acc[it][3];
            float a4 = acc[it][4], a5 = acc[it][5], a6 = acc[it][6], a7 = acc[it][7];
            // s=4
            {
                float s0 = (c & 4) ? a0 : a4, s1 = (c & 4) ? a1 : a5;
                float s2 = (c & 4) ? a2 : a6, s3 = (c & 4) ? a3 : a7;
                float r0 = __shfl_xor_sync(0xffffffffu, s0, 4);
                float r1 = __shfl_xor_sync(0xffffffffu, s1, 4);
                float r2 = __shfl_xor_sync(0xffffffffu, s2, 4);
                float r3 = __shfl_xor_sync(0xffffffffu, s3, 4);
                a0 = ((c & 4) ? a4 : a0) + r0;
                a1 = ((c & 4) ? a5 : a1) + r1;
                a2 = ((c & 4) ? a6 : a2) + r2;
                a3 = ((c & 4) ? a7 : a3) + r3;
            }
            // s=2
            {
                float s0 = (c & 2) ? a0 : a2, s1 = (c & 2) ? a1 : a3;
                float r0 = __shfl_xor_sync(0xffffffffu, s0, 2);
                float r1 = __shfl_xor_sync(0xffffffffu, s1, 2);
                a0 = ((c & 2) ? a2 : a0) + r0;
                a1 = ((c & 2) ? a3 : a1) + r1;
            }
            // s=1
            {
                float s0 = (c & 1) ? a0 : a1;
                float r0 = __shfl_xor_sync(0xffffffffu, s0, 1);
                a0 = ((c & 1) ? a1 : a0) + r0;
            }
            const int tok = c;
            const int rr  = w * 8 + it * 4 + g;
            float v = gelu_exact(a0 + bias[it]);     // once per lane
            if (tok < nt)
                g_h[(size_t)stoks[tok] * H4_DIM + q * 32 + rr] = v;
        }
    }
}

// ============================================================================
// Layer 2: grid = N_NODES*8*NC. bid -> (n, q rows-of-16, tc).
// 128 thr / 4 warps. Warp w owns 4 SEQUENTIAL rows q*16 + w*4 + it.
// Full 32-lane k-split [j*32+lane] (conflict-free); each LDS.128 feeds 4 rows
// (16 FFMA). Tokens in 2 halves of 4 (acc[4][4]) to bound regs.
// ============================================================================
__global__ __launch_bounds__(128, 4)
void layer2_kernel(const float* __restrict__ W2,
                   const float* __restrict__ b2,
                   float* __restrict__ out) {
    __shared__ float hs[TB][H4_DIM];   // 16 KB
    __shared__ int   stoks[TB];

    const int b  = blockIdx.x;
    const int tc = b & (NC - 1);
    const int q  = (b >> 2) & 7;
    const int n  = b >> 5;
    const int base0 = tc * TB;

    const int tid = threadIdx.x;

    int spec_tok = 0;
    if (tid < TB) spec_tok = g_tokens[n * T_TOK + base0 + tid];
    const int nt_total = g_count[n];
    if (base0 >= nt_total) return;

    const int w    = tid >> 5;
    const int lane = tid & 31;

    const int row0 = q * 16 + w * 4;
    const float* W2c = W2 + (size_t)n * H_DIM * H4_DIM + (size_t)row0 * H4_DIM;

    // Weights in regs: 4 rows x 4 float4 = 64 floats/thread
    float4 wv[4][4];
    float  bias[4];
    #pragma unroll
    for (int it = 0; it < 4; it++) {
        const float4* wr = (const float4*)(W2c + (size_t)it * H4_DIM);
        #pragma unroll
        for (int j = 0; j < 4; j++) wv[it][j] = wr[j * 32 + lane];
        bias[it] = b2[n * H_DIM + row0 + it];
    }

    for (int base = base0; base < nt_total; base += NC * TB) {
        const int nt = min(TB, nt_total - base);

        __syncthreads();
        if (tid < nt)
            stoks[tid] = (base == base0) ? spec_tok
                                         : g_tokens[n * T_TOK + base + tid];
        __syncthreads();
        // Stage h rows: nt*128 float4; 128 threads -> up to 8 each (good MLP)
        #pragma unroll
        for (int k = 0; k < 8; k++) {
            int idx = tid + k * 128;
            int tk = idx >> 7;
            int l4 = idx & 127;
            if (tk < nt)
                ((float4*)hs[tk])[l4] =
                    ((const float4*)(g_h + (size_t)stoks[tk] * H4_DIM))[l4];
        }
        __syncthreads();

        #pragma unroll
        for (int h2 = 0; h2 < 2; h2++) {
            float acc[4][4];
            #pragma unroll
            for (int it = 0; it < 4; it++)
                #pragma unroll
                for (int tl = 0; tl < 4; tl++) acc[it][tl] = 0.f;

            #pragma unroll
            for (int tl = 0; tl < 4; tl++) {
                const int t = h2 * 4 + tl;
                if (t < nt) {
                    #pragma unroll
                    for (int j = 0; j < 4; j++) {
                        float4 hv = ((const float4*)hs[t])[j * 32 + lane]; // 1 load -> 4 rows
                        #pragma unroll
                        for (int it = 0; it < 4; it++) {
                            acc[it][tl] += wv[it][j].x * hv.x + wv[it][j].y * hv.y
                                         + wv[it][j].z * hv.z + wv[it][j].w * hv.w;
                        }
                    }
                }
            }

            // Distributing butterfly: token bit1 <- (lane&16), bit0 <- (lane&8);
            // then elementwise reduce over lane bits {4,2,1}.
            #pragma unroll
            for (int it = 0; it < 4; it++) {
                float a0 = acc[it][0], a1 = acc[it][1];
                float a2 = acc[it][2], a3 = acc[it][3];
                {
                    float s0 = (lane & 16) ? a0 : a2, s1 = (lane & 16) ? a1 : a3;
                    float r0 = __shfl_xor_sync(0xffffffffu, s0, 16);
                    float r1 = __shfl_xor_sync(0xffffffffu, s1, 16);
                    a0 = ((lane & 16) ? a2 : a0) + r0;
                    a1 = ((lane & 16) ? a3 : a1) + r1;
                }
                {
                    float s0 = (lane & 8) ? a0 : a1;
                    float r0 = __shfl_xor_sync(0xffffffffu, s0, 8);
                    a0 = ((lane & 8) ? a1 : a0) + r0;
                }
                a0 += __shfl_xor_sync(0xffffffffu, a0, 4);
                a0 += __shfl_xor_sync(0xffffffffu, a0, 2);
                a0 += __shfl_xor_sync(0xffffffffu, a0, 1);

                const int tok = h2 * 4 + (((lane & 16) ? 2 : 0) | ((lane & 8) ? 1 : 0));
                if ((lane & 7) == 0 && tok < nt)
                    out[(size_t)stoks[tok] * H_DIM + row0 + it] = a0 + bias[it];
            }
        }
    }
}

extern "C" void kernel_launch(void* const* d_in, const int* in_sizes, int n_in,
                              void* d_out, int out_size) {
    const float* x        = (const float*)d_in[0];
    const int*   node_ind = (const int*)  d_in[1];
    const float* W1       = (const float*)d_in[2];
    const float* b1       = (const float*)d_in[3];
    const float* W2       = (const float*)d_in[4];
    const float* b2       = (const float*)d_in[5];
    float*       out      = (float*)d_out;

    prep_kernel<<<1, 1024>>>(node_ind);
    layer1_kernel<<<N_NODES * 16 * NC, 128>>>(x, W1, b1);
    layer2_kernel<<<N_NODES * 8 * NC, 128>>>(W2, b2, out);
}